// round 7
// baseline (speedup 1.0000x reference)
#include <cuda_runtime.h>
#include <math.h>

#define EMBED 1024
#define H1D   1024
#define H2D   1024
#define IMG   2048
#define MIDD  512
#define VOCAB 32000
#define NR    576

// ---------------- scratch (device globals; no allocations) ----------------
__device__ float d_x1[4096];          // [h2 | vbar | we]
__device__ float d_g[4096];           // gate pre-activations (reused lstm1/lstm2)
__device__ float d_h1n[H1D];
__device__ float d_h1t[MIDD];         // lh_w @ h1n + lh_b
__device__ float d_apart[32 * NR];    // deterministic attention-logit partials
__device__ float d_aw[NR];            // softmax weights
__device__ float d_x2[IMG + H1D];     // [v | h1n]
__device__ float d_h2n[H2D];

// device-side selectors (host never needs symbol addresses)
#define SRC_X1  0
#define SRC_H1N 1
#define SRC_X2  2
#define SRC_H2N 3
__device__ __forceinline__ const float* sel_src(int s) {
    switch (s) {
        case SRC_X1:  return d_x1;
        case SRC_H1N: return d_h1n;
        case SRC_X2:  return d_x2;
        default:      return d_h2n;
    }
}
#define DST_G   0
#define DST_H1T 1
__device__ __forceinline__ float* sel_dst(int s) {
    return (s == DST_G) ? d_g : d_h1t;
}

// ---------------- setup: vbar mean + x1 assembly ----------------
__global__ void setup_kernel(const float* __restrict__ V, const int* __restrict__ w,
                             const float* __restrict__ h2, const float* __restrict__ emb)
{
    int j = blockIdx.x * blockDim.x + threadIdx.x;   // 0..4095
    if (j < 1024) {
        d_x1[j] = h2[j];
    } else if (j < 1024 + IMG) {
        int col = j - 1024;
        float s0 = 0.f, s1 = 0.f, s2 = 0.f, s3 = 0.f;
        #pragma unroll 4
        for (int i = 0; i < NR; i += 4) {
            s0 += V[(i + 0) * IMG + col];
            s1 += V[(i + 1) * IMG + col];
            s2 += V[(i + 2) * IMG + col];
            s3 += V[(i + 3) * IMG + col];
        }
        d_x1[j] = (s0 + s1 + s2 + s3) * (1.0f / NR);
    } else if (j < 4096) {
        d_x1[j] = emb[(size_t)w[0] * EMBED + (j - (1024 + IMG))];
    }
}

// ---- generic warp-per-row matvec: out = W1*src (+ W2*v2) + b1 (+ b2) ----
// src comes from a device-global selector; out goes to out_ext if non-null,
// else to a device-global selector.
__global__ void matvec_kernel(const float4* __restrict__ W1, int C1_4,
                              const float4* __restrict__ W2, int C2_4,
                              int src_sel,
                              const float*  __restrict__ v2,
                              const float*  __restrict__ b1,
                              const float*  __restrict__ b2,
                              float* __restrict__ out_ext, int dst_sel,
                              int R)
{
    extern __shared__ float xs[];
    const float* v1 = sel_src(src_sel);
    int tid = threadIdx.x;
    for (int i = tid; i < C1_4 * 4; i += blockDim.x) xs[i] = v1[i];
    if (v2) for (int i = tid; i < C2_4 * 4; i += blockDim.x) xs[C1_4 * 4 + i] = v2[i];
    __syncthreads();

    int warp = tid >> 5, lane = tid & 31;
    int r = blockIdx.x * (blockDim.x >> 5) + warp;
    if (r >= R) return;

    const float4* xs4 = (const float4*)xs;
    float acc = 0.f;
    {
        const float4* Wr = W1 + (size_t)r * C1_4;
        #pragma unroll 4
        for (int i = lane; i < C1_4; i += 32) {
            float4 a = Wr[i], x = xs4[i];
            acc += a.x * x.x + a.y * x.y + a.z * x.z + a.w * x.w;
        }
    }
    if (W2) {
        const float4* W2r = W2 + (size_t)r * C2_4;
        const float4* x2s = xs4 + C1_4;
        #pragma unroll 4
        for (int i = lane; i < C2_4; i += 32) {
            float4 a = W2r[i], x = x2s[i];
            acc += a.x * x.x + a.y * x.y + a.z * x.z + a.w * x.w;
        }
    }
    #pragma unroll
    for (int off = 16; off; off >>= 1) acc += __shfl_xor_sync(0xffffffffu, acc, off);
    if (lane == 0) {
        float b = b1 ? b1[r] : 0.f;
        if (b2) b += b2[r];
        float* out = out_ext ? out_ext : sel_dst(dst_sel);
        out[r] = acc + b;
    }
}

// ---------------- LSTM cell from d_g (gate order i,f,g,o) ----------------
// which==1: h -> {hA, d_h1n, d_x2[IMG..]} ; which==2: h -> {hA, d_h2n}
__global__ void lstm_cell_kernel(const float* __restrict__ c_old,
                                 float* __restrict__ hA, float* __restrict__ cA,
                                 int which)
{
    int j = blockIdx.x * blockDim.x + threadIdx.x;   // 0..1023
    float gi = d_g[j], gf = d_g[1024 + j], gg = d_g[2048 + j], go = d_g[3072 + j];
    float i = 1.f / (1.f + expf(-gi));
    float f = 1.f / (1.f + expf(-gf));
    float o = 1.f / (1.f + expf(-go));
    float c = f * c_old[j] + i * tanhf(gg);
    float h = o * tanhf(c);
    cA[j] = c;
    hA[j] = h;
    if (which == 1) {
        d_h1n[j] = h;
        d_x2[IMG + j] = h;
    } else {
        d_h2n[j] = h;
    }
}

// ---------------- attention GEMM + fused logit epilogue ----------------
// Block tile: 16 regions x 16 mids. 4 warps, each warp owns 4 mids; lanes split K.
// logit partial for (mid-block mb, region n) -> d_apart[mb*NR + n] (deterministic).
__global__ void __launch_bounds__(128) attn_kernel(const float* __restrict__ V,
                                                   const float* __restrict__ lv_w,
                                                   const float* __restrict__ lv_b,
                                                   const float* __restrict__ att_w)
{
    const int rb   = blockIdx.x;           // 0..35 (region tiles of 16)
    const int mb   = blockIdx.y;           // 0..31 (mid tiles of 16)
    const int w    = threadIdx.x >> 5;     // warp 0..3
    const int lane = threadIdx.x & 31;
    const int r0 = rb * 16;
    const int m0 = mb * 16 + w * 4;

    __shared__ float Vs[16][128];
    __shared__ float part[4][16];

    float acc[4][16];
    #pragma unroll
    for (int mi = 0; mi < 4; mi++)
        #pragma unroll
        for (int r = 0; r < 16; r++) acc[mi][r] = 0.f;

    for (int k0 = 0; k0 < IMG; k0 += 128) {
        __syncthreads();
        #pragma unroll
        for (int jj = 0; jj < 16; jj++)
            Vs[jj][threadIdx.x] = V[(size_t)(r0 + jj) * IMG + k0 + threadIdx.x];
        __syncthreads();

        #pragma unroll
        for (int kk4 = 0; kk4 < 4; kk4++) {
            int kk = kk4 * 32 + lane;
            float lw[4];
            #pragma unroll
            for (int mi = 0; mi < 4; mi++)
                lw[mi] = lv_w[(size_t)(m0 + mi) * IMG + k0 + kk];
            #pragma unroll
            for (int r = 0; r < 16; r++) {
                float v = Vs[r][kk];
                #pragma unroll
                for (int mi = 0; mi < 4; mi++) acc[mi][r] += lw[mi] * v;
            }
        }
    }

    // all-reduce each accumulator across lanes (K-slices); result lane-uniform
    #pragma unroll
    for (int mi = 0; mi < 4; mi++)
        #pragma unroll
        for (int r = 0; r < 16; r++) {
            float s = acc[mi][r];
            #pragma unroll
            for (int off = 16; off; off >>= 1) s += __shfl_xor_sync(0xffffffffu, s, off);
            acc[mi][r] = s;
        }

    // epilogue: 16 lanes each handle one region (tanh work spread across lanes)
    if (lane < 16) {
        int r = lane;
        float p = att_w[m0 + 0] * tanhf(acc[0][r] + lv_b[m0 + 0] + d_h1t[m0 + 0])
                + att_w[m0 + 1] * tanhf(acc[1][r] + lv_b[m0 + 1] + d_h1t[m0 + 1])
                + att_w[m0 + 2] * tanhf(acc[2][r] + lv_b[m0 + 2] + d_h1t[m0 + 2])
                + att_w[m0 + 3] * tanhf(acc[3][r] + lv_b[m0 + 3] + d_h1t[m0 + 3]);
        part[w][r] = p;
    }
    __syncthreads();
    if (threadIdx.x < 16) {
        int r = threadIdx.x;
        d_apart[mb * NR + r0 + r] = part[0][r] + part[1][r] + part[2][r] + part[3][r];
    }
}

// ---------------- softmax over 576 regions (one block) ----------------
__global__ void softmax_kernel(const float* __restrict__ att_b)
{
    __shared__ float red[1024];
    int t = threadIdx.x;
    float lv = 0.f, logit = -1e30f;
    if (t < NR) {
        lv = att_b[0];
        #pragma unroll 8
        for (int mbb = 0; mbb < 32; mbb++) lv += d_apart[mbb * NR + t];
        logit = lv;
    }
    red[t] = logit;
    __syncthreads();
    for (int s = 512; s; s >>= 1) { if (t < s) red[t] = fmaxf(red[t], red[t + s]); __syncthreads(); }
    float mx = red[0];
    __syncthreads();
    float e = (t < NR) ? expf(lv - mx) : 0.f;
    red[t] = e;
    __syncthreads();
    for (int s = 512; s; s >>= 1) { if (t < s) red[t] += red[t + s]; __syncthreads(); }
    float inv = 1.f / red[0];
    if (t < NR) d_aw[t] = e * inv;
}

// ---------------- v = sum_n a_n * V_n  -> x2[0:2048] ----------------
__global__ void att_apply_kernel(const float* __restrict__ V)
{
    __shared__ float aw[NR];
    for (int i = threadIdx.x; i < NR; i += blockDim.x) aw[i] = d_aw[i];
    __syncthreads();
    int j = blockIdx.x * blockDim.x + threadIdx.x;   // 0..2047
    float s0 = 0.f, s1 = 0.f;
    #pragma unroll 2
    for (int n = 0; n < NR; n += 2) {
        s0 += aw[n]     * V[(size_t)n * IMG + j];
        s1 += aw[n + 1] * V[(size_t)(n + 1) * IMG + j];
    }
    d_x2[j] = s0 + s1;
}

// ---------------- launch ----------------
extern "C" void kernel_launch(void* const* d_in, const int* in_sizes, int n_in,
                              void* d_out, int out_size)
{
    const float* V      = (const float*)d_in[0];
    const int*   w      = (const int*)  d_in[1];
    const float* h1     = (const float*)d_in[2];
    const float* c1     = (const float*)d_in[3];
    const float* h2     = (const float*)d_in[4];
    const float* c2     = (const float*)d_in[5];
    const float* emb    = (const float*)d_in[6];
    const float* W_ih1  = (const float*)d_in[7];
    const float* W_hh1  = (const float*)d_in[8];
    const float* b_ih1  = (const float*)d_in[9];
    const float* b_hh1  = (const float*)d_in[10];
    const float* W_ih2  = (const float*)d_in[11];
    const float* W_hh2  = (const float*)d_in[12];
    const float* b_ih2  = (const float*)d_in[13];
    const float* b_hh2  = (const float*)d_in[14];
    const float* lv_w   = (const float*)d_in[15];
    const float* lv_b   = (const float*)d_in[16];
    const float* lh_w   = (const float*)d_in[17];
    const float* lh_b   = (const float*)d_in[18];
    const float* att_w  = (const float*)d_in[19];
    const float* att_b  = (const float*)d_in[20];
    const float* lin_w  = (const float*)d_in[21];
    const float* lin_b  = (const float*)d_in[22];

    float* out   = (float*)d_out;
    float* o_out   = out;            // 32000
    float* h1n_out = out + 32000;    // 1024
    float* c1n_out = out + 33024;    // 1024
    float* h2n_out = out + 34048;    // 1024
    float* c2n_out = out + 35072;    // 1024

    // 1. x1 = [h2 | mean(V) | emb[w]]
    setup_kernel<<<16, 256>>>(V, w, h2, emb);

    // 2. g = W_ih1 x1 + b_ih1 + W_hh1 h1 + b_hh1      (4096 rows)
    matvec_kernel<<<512, 256, (4096 + 1024) * sizeof(float)>>>(
        (const float4*)W_ih1, 4096 / 4, (const float4*)W_hh1, 1024 / 4,
        SRC_X1, h1, b_ih1, b_hh1, nullptr, DST_G, 4096);

    // 3. LSTM1 cell -> h1n (out + scratch + x2 tail), c1n (out)
    lstm_cell_kernel<<<4, 256>>>(c1, h1n_out, c1n_out, 1);

    // 4. h1t = lh_w h1n + lh_b                        (512 rows)
    matvec_kernel<<<64, 256, 1024 * sizeof(float)>>>(
        (const float4*)lh_w, 1024 / 4, (const float4*)nullptr, 0,
        SRC_H1N, nullptr, lh_b, nullptr, nullptr, DST_H1T, 512);

    // 5. attention GEMM + logit partials
    dim3 agrid(36, 32);
    attn_kernel<<<agrid, 128>>>(V, lv_w, lv_b, att_w);

    // 6. softmax over regions
    softmax_kernel<<<1, 1024>>>(att_b);

    // 7. v = sum a_n V_n -> x2 head
    att_apply_kernel<<<8, 256>>>(V);

    // 8. g = W_ih2 x2 + b_ih2 + W_hh2 h2 + b_hh2      (4096 rows)
    matvec_kernel<<<512, 256, (3072 + 1024) * sizeof(float)>>>(
        (const float4*)W_ih2, 3072 / 4, (const float4*)W_hh2, 1024 / 4,
        SRC_X2, h2, b_ih2, b_hh2, nullptr, DST_G, 4096);

    // 9. LSTM2 cell -> h2n, c2n
    lstm_cell_kernel<<<4, 256>>>(c2, h2n_out, c2n_out, 2);

    // 10. o = lin_w h2n + lin_b                       (32000 rows)
    matvec_kernel<<<4000, 256, 1024 * sizeof(float)>>>(
        (const float4*)lin_w, 1024 / 4, (const float4*)nullptr, 0,
        SRC_H2N, nullptr, lin_b, nullptr, o_out, 0, 32000);
}

// round 8
// speedup vs baseline: 1.3165x; 1.3165x over previous
#include <cuda_runtime.h>
#include <math.h>

#define EMBED 1024
#define H1D   1024
#define H2D   1024
#define IMG   2048
#define MIDD  512
#define VOCAB 32000
#define NR    576
#define RCHUNKS 18            // 576 / 32

// ---------------- scratch (device globals; no allocations) ----------------
__device__ float d_x1[4096];             // [h2 | vbar | we]
__device__ float d_g[4096];              // gate pre-activations
__device__ float d_h1n[H1D];
__device__ float d_h1t[MIDD];
__device__ float d_vt[NR * MIDD];        // raw attention GEMM result
__device__ float d_alog[NR];             // attention logits
__device__ float d_aw[NR];               // softmax weights
__device__ float d_vpart[RCHUNKS * IMG]; // vbar partials
__device__ float d_x2part[RCHUNKS * IMG];// attended-v partials
__device__ float d_x2[IMG + H1D];        // [v | h1n]
__device__ float d_h2n[H2D];

#define SRC_X1  0
#define SRC_X2  2
#define SRC_H2N 3
__device__ __forceinline__ const float* sel_src(int s) {
    switch (s) {
        case SRC_X1:  return d_x1;
        case SRC_X2:  return d_x2;
        default:      return d_h2n;
    }
}

// ---------------- vbar partials: 18 row-chunks x 2048 cols ----------------
__global__ void vbar_part_kernel(const float* __restrict__ V)
{
    int rc  = blockIdx.y;                          // 0..17
    int col = blockIdx.x * 256 + threadIdx.x;      // 0..2047
    const float* Vp = V + (size_t)rc * 32 * IMG + col;
    float s = 0.f;
    #pragma unroll 8
    for (int i = 0; i < 32; i++) s += Vp[(size_t)i * IMG];
    d_vpart[rc * IMG + col] = s;
}

// ---------------- x1 = [h2 | vbar | emb[w]] ----------------
__global__ void x1_kernel(const int* __restrict__ w, const float* __restrict__ h2,
                          const float* __restrict__ emb)
{
    int j = blockIdx.x * blockDim.x + threadIdx.x;   // 0..4095
    if (j < 1024) {
        d_x1[j] = h2[j];
    } else if (j < 1024 + IMG) {
        int c = j - 1024;
        float s = 0.f;
        #pragma unroll
        for (int rc = 0; rc < RCHUNKS; rc++) s += d_vpart[rc * IMG + c];
        d_x1[j] = s * (1.0f / NR);
    } else if (j < 4096) {
        d_x1[j] = emb[(size_t)w[0] * EMBED + (j - (1024 + IMG))];
    }
}

// ---- warp-per-row matvec, 8-deep load pipeline ----
__global__ void matvec_kernel(const float4* __restrict__ W1, int C1_4,
                              const float4* __restrict__ W2, int C2_4,
                              int src_sel,
                              const float*  __restrict__ v2,
                              const float*  __restrict__ b1,
                              const float*  __restrict__ b2,
                              float* __restrict__ out_ext,
                              int R)
{
    extern __shared__ float xs[];
    const float* v1 = sel_src(src_sel);
    int tid = threadIdx.x;
    for (int i = tid; i < C1_4 * 4; i += blockDim.x) xs[i] = v1[i];
    if (v2) for (int i = tid; i < C2_4 * 4; i += blockDim.x) xs[C1_4 * 4 + i] = v2[i];
    __syncthreads();

    int warp = tid >> 5, lane = tid & 31;
    int r = blockIdx.x * (blockDim.x >> 5) + warp;
    if (r >= R) return;

    const float4* xs4 = (const float4*)xs;
    float acc = 0.f;
    {
        const float4* Wr = W1 + (size_t)r * C1_4;
        int i = lane;
        for (; i + 7 * 32 < C1_4; i += 8 * 32) {
            float4 a[8];
            #pragma unroll
            for (int u = 0; u < 8; u++) a[u] = Wr[i + u * 32];
            #pragma unroll
            for (int u = 0; u < 8; u++) {
                float4 x = xs4[i + u * 32];
                acc += a[u].x * x.x + a[u].y * x.y + a[u].z * x.z + a[u].w * x.w;
            }
        }
        for (; i < C1_4; i += 32) {
            float4 a = Wr[i], x = xs4[i];
            acc += a.x * x.x + a.y * x.y + a.z * x.z + a.w * x.w;
        }
    }
    if (W2) {
        const float4* W2r = W2 + (size_t)r * C2_4;
        const float4* x2s = xs4 + C1_4;
        int i = lane;
        for (; i + 7 * 32 < C2_4; i += 8 * 32) {
            float4 a[8];
            #pragma unroll
            for (int u = 0; u < 8; u++) a[u] = W2r[i + u * 32];
            #pragma unroll
            for (int u = 0; u < 8; u++) {
                float4 x = x2s[i + u * 32];
                acc += a[u].x * x.x + a[u].y * x.y + a[u].z * x.z + a[u].w * x.w;
            }
        }
        for (; i < C2_4; i += 32) {
            float4 a = W2r[i], x = x2s[i];
            acc += a.x * x.x + a.y * x.y + a.z * x.z + a.w * x.w;
        }
    }
    #pragma unroll
    for (int off = 16; off; off >>= 1) acc += __shfl_xor_sync(0xffffffffu, acc, off);
    if (lane == 0) {
        float b = b1 ? b1[r] : 0.f;
        if (b2) b += b2[r];
        float* out = out_ext ? out_ext : d_g;
        out[r] = acc + b;
    }
}

// ---------------- h1t = lh_w @ h1n + lh_b  (block per row) ----------------
__global__ void h1t_kernel(const float4* __restrict__ lh_w, const float* __restrict__ lh_b)
{
    int r = blockIdx.x;                 // 0..511
    int t = threadIdx.x;                // 0..127
    const float4* Wr = lh_w + (size_t)r * 256;
    const float4* x4 = (const float4*)d_h1n;
    float4 a0 = Wr[t], a1 = Wr[t + 128];
    float4 x0 = x4[t], x1 = x4[t + 128];
    float s = a0.x * x0.x + a0.y * x0.y + a0.z * x0.z + a0.w * x0.w
            + a1.x * x1.x + a1.y * x1.y + a1.z * x1.z + a1.w * x1.w;
    #pragma unroll
    for (int o = 16; o; o >>= 1) s += __shfl_xor_sync(0xffffffffu, s, o);
    __shared__ float ws[4];
    if ((t & 31) == 0) ws[t >> 5] = s;
    __syncthreads();
    if (t == 0) d_h1t[r] = ws[0] + ws[1] + ws[2] + ws[3] + lh_b[r];
}

// ---------------- LSTM cell from d_g (gate order i,f,g,o) ----------------
__global__ void lstm_cell_kernel(const float* __restrict__ c_old,
                                 float* __restrict__ hA, float* __restrict__ cA,
                                 int which)
{
    int j = blockIdx.x * blockDim.x + threadIdx.x;   // 0..1023
    float gi = d_g[j], gf = d_g[1024 + j], gg = d_g[2048 + j], go = d_g[3072 + j];
    float i = 1.f / (1.f + expf(-gi));
    float f = 1.f / (1.f + expf(-gf));
    float o = 1.f / (1.f + expf(-go));
    float c = f * c_old[j] + i * tanhf(gg);
    float h = o * tanhf(c);
    cA[j] = c;
    hA[j] = h;
    if (which == 1) {
        d_h1n[j] = h;
        d_x2[IMG + j] = h;
    } else {
        d_h2n[j] = h;
    }
}

// ---------------- attention GEMM: vt[n][m] = V[n,:] . lv_w[m,:] ----------------
// 16 regions x 16 mids per block; 4 warps each own 4 mids; lanes split K.
// Accumulators stay in registers: all indexing is compile-time constant.
__global__ void __launch_bounds__(128) attn_gemm_kernel(const float* __restrict__ V,
                                                        const float* __restrict__ lv_w)
{
    const int rb   = blockIdx.x;           // 0..35
    const int mb   = blockIdx.y;           // 0..31
    const int w    = threadIdx.x >> 5;
    const int lane = threadIdx.x & 31;
    const int r0 = rb * 16;
    const int m0 = mb * 16 + w * 4;

    __shared__ float Vs[16][128];

    float acc[4][16];
    #pragma unroll
    for (int mi = 0; mi < 4; mi++)
        #pragma unroll
        for (int r = 0; r < 16; r++) acc[mi][r] = 0.f;

    for (int k0 = 0; k0 < IMG; k0 += 128) {
        __syncthreads();
        #pragma unroll
        for (int jj = 0; jj < 16; jj++)
            Vs[jj][threadIdx.x] = V[(size_t)(r0 + jj) * IMG + k0 + threadIdx.x];
        __syncthreads();

        #pragma unroll
        for (int kk4 = 0; kk4 < 4; kk4++) {
            int kk = kk4 * 32 + lane;
            float lw[4];
            #pragma unroll
            for (int mi = 0; mi < 4; mi++)
                lw[mi] = lv_w[(size_t)(m0 + mi) * IMG + k0 + kk];
            #pragma unroll
            for (int r = 0; r < 16; r++) {
                float v = Vs[r][kk];
                #pragma unroll
                for (int mi = 0; mi < 4; mi++) acc[mi][r] += lw[mi] * v;
            }
        }
    }

    // lane all-reduce (K slices) -> lane-uniform values
    #pragma unroll
    for (int mi = 0; mi < 4; mi++)
        #pragma unroll
        for (int r = 0; r < 16; r++) {
            float s = acc[mi][r];
            #pragma unroll
            for (int off = 16; off; off >>= 1) s += __shfl_xor_sync(0xffffffffu, s, off);
            acc[mi][r] = s;
        }

    // statically-indexed predicated stores (keeps acc in registers)
    #pragma unroll
    for (int r = 0; r < 16; r++) {
        if (lane == r) {
            #pragma unroll
            for (int mi = 0; mi < 4; mi++)
                d_vt[(size_t)(r0 + r) * MIDD + m0 + mi] = acc[mi][r];
        }
    }
}

// ---------------- logits: a_n = att_w . tanh(vt[n] + h1t + lv_b) + att_b ----
__global__ void logits_kernel(const float* __restrict__ lv_b,
                              const float* __restrict__ att_w,
                              const float* __restrict__ att_b)
{
    __shared__ float hb[MIDD];
    __shared__ float aww[MIDD];
    for (int i = threadIdx.x; i < MIDD; i += 128) {
        hb[i]  = d_h1t[i] + lv_b[i];
        aww[i] = att_w[i];
    }
    __syncthreads();
    int warp = threadIdx.x >> 5, lane = threadIdx.x & 31;
    int wg = blockIdx.x * 4 + warp;        // 0..143
    #pragma unroll
    for (int q = 0; q < 4; q++) {
        int n = wg * 4 + q;                // 0..575
        const float* vtn = d_vt + (size_t)n * MIDD;
        float s = 0.f;
        for (int m = lane; m < MIDD; m += 32)
            s += aww[m] * tanhf(vtn[m] + hb[m]);
        #pragma unroll
        for (int off = 16; off; off >>= 1) s += __shfl_xor_sync(0xffffffffu, s, off);
        if (lane == 0) d_alog[n] = s + att_b[0];
    }
}

// ---------------- softmax over 576 regions (one block) ----------------
__global__ void softmax_kernel()
{
    __shared__ float red[1024];
    int t = threadIdx.x;
    float lv = 0.f, logit = -1e30f;
    if (t < NR) { lv = d_alog[t]; logit = lv; }
    red[t] = logit;
    __syncthreads();
    for (int s = 512; s; s >>= 1) { if (t < s) red[t] = fmaxf(red[t], red[t + s]); __syncthreads(); }
    float mx = red[0];
    __syncthreads();
    float e = (t < NR) ? expf(lv - mx) : 0.f;
    red[t] = e;
    __syncthreads();
    for (int s = 512; s; s >>= 1) { if (t < s) red[t] += red[t + s]; __syncthreads(); }
    float inv = 1.f / red[0];
    if (t < NR) d_aw[t] = e * inv;
}

// ---------------- attended v partials: 18 row-chunks ----------------
__global__ void apply_part_kernel(const float* __restrict__ V)
{
    int rc  = blockIdx.y;                          // 0..17
    int col = blockIdx.x * 256 + threadIdx.x;      // 0..2047
    __shared__ float aw[32];
    if (threadIdx.x < 32) aw[threadIdx.x] = d_aw[rc * 32 + threadIdx.x];
    __syncthreads();
    const float* Vp = V + (size_t)rc * 32 * IMG + col;
    float s = 0.f;
    #pragma unroll 8
    for (int i = 0; i < 32; i++) s += aw[i] * Vp[(size_t)i * IMG];
    d_x2part[rc * IMG + col] = s;
}

__global__ void apply_reduce_kernel()
{
    int j = blockIdx.x * 256 + threadIdx.x;        // 0..2047
    float s = 0.f;
    #pragma unroll
    for (int rc = 0; rc < RCHUNKS; rc++) s += d_x2part[rc * IMG + j];
    d_x2[j] = s;
}

// ---------------- launch ----------------
extern "C" void kernel_launch(void* const* d_in, const int* in_sizes, int n_in,
                              void* d_out, int out_size)
{
    const float* V      = (const float*)d_in[0];
    const int*   w      = (const int*)  d_in[1];
    const float* h1     = (const float*)d_in[2];
    const float* c1     = (const float*)d_in[3];
    const float* h2     = (const float*)d_in[4];
    const float* c2     = (const float*)d_in[5];
    const float* emb    = (const float*)d_in[6];
    const float* W_ih1  = (const float*)d_in[7];
    const float* W_hh1  = (const float*)d_in[8];
    const float* b_ih1  = (const float*)d_in[9];
    const float* b_hh1  = (const float*)d_in[10];
    const float* W_ih2  = (const float*)d_in[11];
    const float* W_hh2  = (const float*)d_in[12];
    const float* b_ih2  = (const float*)d_in[13];
    const float* b_hh2  = (const float*)d_in[14];
    const float* lv_w   = (const float*)d_in[15];
    const float* lv_b   = (const float*)d_in[16];
    const float* lh_w   = (const float*)d_in[17];
    const float* lh_b   = (const float*)d_in[18];
    const float* att_w  = (const float*)d_in[19];
    const float* att_b  = (const float*)d_in[20];
    const float* lin_w  = (const float*)d_in[21];
    const float* lin_b  = (const float*)d_in[22];

    float* out     = (float*)d_out;
    float* o_out   = out;            // 32000
    float* h1n_out = out + 32000;
    float* c1n_out = out + 33024;
    float* h2n_out = out + 34048;
    float* c2n_out = out + 35072;

    // one-time side stream + fork/join events (created outside capture on the
    // correctness call; reused identically on every call)
    static cudaStream_t s_side = nullptr;
    static cudaEvent_t ev_fork = nullptr, ev_join = nullptr;
    if (!s_side) {
        cudaStreamCreateWithFlags(&s_side, cudaStreamNonBlocking);
        cudaEventCreateWithFlags(&ev_fork, cudaEventDisableTiming);
        cudaEventCreateWithFlags(&ev_join, cudaEventDisableTiming);
    }

    // ---- fork: attention GEMM (depends only on V, lv_w) on side stream ----
    cudaEventRecord(ev_fork, 0);
    cudaStreamWaitEvent(s_side, ev_fork, 0);
    {
        dim3 agrid(36, 32);
        attn_gemm_kernel<<<agrid, 128, 0, s_side>>>(V, lv_w);
    }
    cudaEventRecord(ev_join, s_side);

    // ---- main chain: LSTM1 path ----
    vbar_part_kernel<<<dim3(8, RCHUNKS), 256>>>(V);
    x1_kernel<<<16, 256>>>(w, h2, emb);

    matvec_kernel<<<512, 256, (4096 + 1024) * sizeof(float)>>>(
        (const float4*)W_ih1, 4096 / 4, (const float4*)W_hh1, 1024 / 4,
        SRC_X1, h1, b_ih1, b_hh1, nullptr, 4096);

    lstm_cell_kernel<<<4, 256>>>(c1, h1n_out, c1n_out, 1);

    h1t_kernel<<<512, 128>>>((const float4*)lh_w, lh_b);

    // ---- join: logits need vt + h1t ----
    cudaStreamWaitEvent(0, ev_join, 0);
    logits_kernel<<<36, 128>>>(lv_b, att_w, att_b);
    softmax_kernel<<<1, 1024>>>();
    apply_part_kernel<<<dim3(8, RCHUNKS), 256>>>(V);
    apply_reduce_kernel<<<8, 256>>>();

    matvec_kernel<<<512, 256, (3072 + 1024) * sizeof(float)>>>(
        (const float4*)W_ih2, 3072 / 4, (const float4*)W_hh2, 1024 / 4,
        SRC_X2, h2, b_ih2, b_hh2, nullptr, 4096);

    lstm_cell_kernel<<<4, 256>>>(c2, h2n_out, c2n_out, 2);

    matvec_kernel<<<4000, 256, 1024 * sizeof(float)>>>(
        (const float4*)lin_w, 1024 / 4, (const float4*)nullptr, 0,
        SRC_H2N, nullptr, lin_b, nullptr, o_out, 32000);
}

// round 9
// speedup vs baseline: 1.6662x; 1.2656x over previous
#include <cuda_runtime.h>
#include <math.h>

#define EMBED 1024
#define H1D   1024
#define H2D   1024
#define IMG   2048
#define MIDD  512
#define VOCAB 32000
#define NR    576
#define RCHUNKS 18            // 576 / 32

// ---------------- scratch (device globals; no allocations) ----------------
__device__ float d_x1[4096];             // [h2 | vbar | we]
__device__ float d_g[4096];              // gate pre-activations
__device__ float d_h1n[H1D];
__device__ float d_h1t[MIDD];
__device__ float d_vt[NR * MIDD];        // raw attention GEMM result
__device__ float d_alog[NR];             // attention logits
__device__ float d_aw[NR];               // softmax weights
__device__ float d_vpart[RCHUNKS * IMG]; // vbar partials
__device__ float d_x2part[RCHUNKS * IMG];// attended-v partials
__device__ float d_x2[IMG + H1D];        // [v | h1n]
__device__ float d_h2n[H2D];

#define SRC_X1  0
#define SRC_X2  2
__device__ __forceinline__ const float* sel_src(int s) {
    return (s == SRC_X1) ? d_x1 : d_x2;
}

// ---------------- vbar partials: 18 row-chunks x 2048 cols ----------------
__global__ void vbar_part_kernel(const float* __restrict__ V)
{
    int rc  = blockIdx.y;                          // 0..17
    int col = blockIdx.x * 256 + threadIdx.x;      // 0..2047
    const float* Vp = V + (size_t)rc * 32 * IMG + col;
    float s = 0.f;
    #pragma unroll 8
    for (int i = 0; i < 32; i++) s += Vp[(size_t)i * IMG];
    d_vpart[rc * IMG + col] = s;
}

// ---------------- x1 = [h2 | vbar | emb[w]] ----------------
__global__ void x1_kernel(const int* __restrict__ w, const float* __restrict__ h2,
                          const float* __restrict__ emb)
{
    int j = blockIdx.x * blockDim.x + threadIdx.x;   // 0..4095
    if (j < 1024) {
        d_x1[j] = h2[j];
    } else if (j < 1024 + IMG) {
        int c = j - 1024;
        float s = 0.f;
        #pragma unroll
        for (int rc = 0; rc < RCHUNKS; rc++) s += d_vpart[rc * IMG + c];
        d_x1[j] = s * (1.0f / NR);
    } else if (j < 4096) {
        d_x1[j] = emb[(size_t)w[0] * EMBED + (j - (1024 + IMG))];
    }
}

// ---- LSTM gate matvec, K-split-2: 2 warps per row, 4 rows per 256-thr block ----
// d_g[r] = W1[r,:].x + W2[r,:].v2 + b1[r] + b2[r]
__global__ void matvec2_kernel(const float4* __restrict__ W1, int C1_4,
                               const float4* __restrict__ W2, int C2_4,
                               int src_sel,
                               const float*  __restrict__ v2,
                               const float*  __restrict__ b1,
                               const float*  __restrict__ b2)
{
    extern __shared__ float xs[];
    __shared__ float sp[8];
    const float* v1 = sel_src(src_sel);
    int tid = threadIdx.x;
    for (int i = tid; i < C1_4 * 4; i += blockDim.x) xs[i] = v1[i];
    for (int i = tid; i < C2_4 * 4; i += blockDim.x) xs[C1_4 * 4 + i] = v2[i];
    __syncthreads();

    const int warp = tid >> 5, lane = tid & 31;
    const int row  = blockIdx.x * 4 + (warp >> 1);
    const int half = warp & 1;
    const float4* xs4 = (const float4*)xs;

    float acc = 0.f;
    {
        const int Ch = C1_4 >> 1;
        const float4* Wr = W1 + (size_t)row * C1_4 + half * Ch;
        const float4* xh = xs4 + half * Ch;
        int i = lane;
        for (; i + 7 * 32 < Ch; i += 8 * 32) {
            float4 a[8];
            #pragma unroll
            for (int u = 0; u < 8; u++) a[u] = Wr[i + u * 32];
            #pragma unroll
            for (int u = 0; u < 8; u++) {
                float4 x = xh[i + u * 32];
                acc += a[u].x * x.x + a[u].y * x.y + a[u].z * x.z + a[u].w * x.w;
            }
        }
        for (; i < Ch; i += 32) {
            float4 a = Wr[i], x = xh[i];
            acc += a.x * x.x + a.y * x.y + a.z * x.z + a.w * x.w;
        }
    }
    {
        const int Ch = C2_4 >> 1;
        const float4* Wr = W2 + (size_t)row * C2_4 + half * Ch;
        const float4* xh = xs4 + C1_4 + half * Ch;
        int i = lane;
        for (; i + 3 * 32 < Ch; i += 4 * 32) {
            float4 a[4];
            #pragma unroll
            for (int u = 0; u < 4; u++) a[u] = Wr[i + u * 32];
            #pragma unroll
            for (int u = 0; u < 4; u++) {
                float4 x = xh[i + u * 32];
                acc += a[u].x * x.x + a[u].y * x.y + a[u].z * x.z + a[u].w * x.w;
            }
        }
        for (; i < Ch; i += 32) {
            float4 a = Wr[i], x = xh[i];
            acc += a.x * x.x + a.y * x.y + a.z * x.z + a.w * x.w;
        }
    }
    #pragma unroll
    for (int off = 16; off; off >>= 1) acc += __shfl_xor_sync(0xffffffffu, acc, off);
    if (lane == 0) sp[warp] = acc;
    __syncthreads();
    if (tid < 4) {
        int r = blockIdx.x * 4 + tid;
        d_g[r] = sp[2 * tid] + sp[2 * tid + 1] + b1[r] + b2[r];
    }
}

// ---- vocab projection: warp-per-row (32000 warps -> full occupancy) ----
__global__ void lin_kernel(const float4* __restrict__ W, const float* __restrict__ b,
                           float* __restrict__ out, int R)
{
    __shared__ float xs[H2D];
    int tid = threadIdx.x;
    for (int i = tid; i < H2D; i += blockDim.x) xs[i] = d_h2n[i];
    __syncthreads();

    int warp = tid >> 5, lane = tid & 31;
    int r = blockIdx.x * (blockDim.x >> 5) + warp;
    if (r >= R) return;

    const float4* xs4 = (const float4*)xs;
    const float4* Wr = W + (size_t)r * 256;
    float acc = 0.f;
    {
        float4 a[8];
        #pragma unroll
        for (int u = 0; u < 8; u++) a[u] = Wr[lane + u * 32];
        #pragma unroll
        for (int u = 0; u < 8; u++) {
            float4 x = xs4[lane + u * 32];
            acc += a[u].x * x.x + a[u].y * x.y + a[u].z * x.z + a[u].w * x.w;
        }
    }
    #pragma unroll
    for (int off = 16; off; off >>= 1) acc += __shfl_xor_sync(0xffffffffu, acc, off);
    if (lane == 0) out[r] = acc + b[r];
}

// ---------------- h1t = lh_w @ h1n + lh_b  (block per row) ----------------
__global__ void h1t_kernel(const float4* __restrict__ lh_w, const float* __restrict__ lh_b)
{
    int r = blockIdx.x;                 // 0..511
    int t = threadIdx.x;                // 0..127
    const float4* Wr = lh_w + (size_t)r * 256;
    const float4* x4 = (const float4*)d_h1n;
    float4 a0 = Wr[t], a1 = Wr[t + 128];
    float4 x0 = x4[t], x1 = x4[t + 128];
    float s = a0.x * x0.x + a0.y * x0.y + a0.z * x0.z + a0.w * x0.w
            + a1.x * x1.x + a1.y * x1.y + a1.z * x1.z + a1.w * x1.w;
    #pragma unroll
    for (int o = 16; o; o >>= 1) s += __shfl_xor_sync(0xffffffffu, s, o);
    __shared__ float ws[4];
    if ((t & 31) == 0) ws[t >> 5] = s;
    __syncthreads();
    if (t == 0) d_h1t[r] = ws[0] + ws[1] + ws[2] + ws[3] + lh_b[r];
}

// ---------------- LSTM cell from d_g (gate order i,f,g,o) ----------------
__global__ void lstm_cell_kernel(const float* __restrict__ c_old,
                                 float* __restrict__ hA, float* __restrict__ cA,
                                 int which)
{
    int j = blockIdx.x * blockDim.x + threadIdx.x;   // 0..1023
    float gi = d_g[j], gf = d_g[1024 + j], gg = d_g[2048 + j], go = d_g[3072 + j];
    float i = 1.f / (1.f + expf(-gi));
    float f = 1.f / (1.f + expf(-gf));
    float o = 1.f / (1.f + expf(-go));
    float c = f * c_old[j] + i * tanhf(gg);
    float h = o * tanhf(c);
    cA[j] = c;
    hA[j] = h;
    if (which == 1) {
        d_h1n[j] = h;
        d_x2[IMG + j] = h;
    } else {
        d_h2n[j] = h;
    }
}

// ---------------- attention GEMM: vt[n][m] = V[n,:] . lv_w[m,:] ----------------
__global__ void __launch_bounds__(128) attn_gemm_kernel(const float* __restrict__ V,
                                                        const float* __restrict__ lv_w)
{
    const int rb   = blockIdx.x;           // 0..35
    const int mb   = blockIdx.y;           // 0..31
    const int w    = threadIdx.x >> 5;
    const int lane = threadIdx.x & 31;
    const int r0 = rb * 16;
    const int m0 = mb * 16 + w * 4;

    __shared__ float Vs[16][128];

    float acc[4][16];
    #pragma unroll
    for (int mi = 0; mi < 4; mi++)
        #pragma unroll
        for (int r = 0; r < 16; r++) acc[mi][r] = 0.f;

    for (int k0 = 0; k0 < IMG; k0 += 128) {
        __syncthreads();
        #pragma unroll
        for (int jj = 0; jj < 16; jj++)
            Vs[jj][threadIdx.x] = V[(size_t)(r0 + jj) * IMG + k0 + threadIdx.x];
        __syncthreads();

        #pragma unroll
        for (int kk4 = 0; kk4 < 4; kk4++) {
            int kk = kk4 * 32 + lane;
            float lw[4];
            #pragma unroll
            for (int mi = 0; mi < 4; mi++)
                lw[mi] = lv_w[(size_t)(m0 + mi) * IMG + k0 + kk];
            #pragma unroll
            for (int r = 0; r < 16; r++) {
                float v = Vs[r][kk];
                #pragma unroll
                for (int mi = 0; mi < 4; mi++) acc[mi][r] += lw[mi] * v;
            }
        }
    }

    #pragma unroll
    for (int mi = 0; mi < 4; mi++)
        #pragma unroll
        for (int r = 0; r < 16; r++) {
            float s = acc[mi][r];
            #pragma unroll
            for (int off = 16; off; off >>= 1) s += __shfl_xor_sync(0xffffffffu, s, off);
            acc[mi][r] = s;
        }

    #pragma unroll
    for (int r = 0; r < 16; r++) {
        if (lane == r) {
            #pragma unroll
            for (int mi = 0; mi < 4; mi++)
                d_vt[(size_t)(r0 + r) * MIDD + m0 + mi] = acc[mi][r];
        }
    }
}

// ---------------- logits (att_b dropped: softmax-invariant) ----------------
__global__ void logits_kernel(const float* __restrict__ lv_b,
                              const float* __restrict__ att_w)
{
    __shared__ float hb[MIDD];
    __shared__ float aww[MIDD];
    for (int i = threadIdx.x; i < MIDD; i += 128) {
        hb[i]  = d_h1t[i] + lv_b[i];
        aww[i] = att_w[i];
    }
    __syncthreads();
    int warp = threadIdx.x >> 5, lane = threadIdx.x & 31;
    int wg = blockIdx.x * 4 + warp;        // 0..143
    #pragma unroll
    for (int q = 0; q < 4; q++) {
        int n = wg * 4 + q;                // 0..575
        const float* vtn = d_vt + (size_t)n * MIDD;
        float s = 0.f;
        for (int m = lane; m < MIDD; m += 32)
            s += aww[m] * tanhf(vtn[m] + hb[m]);
        #pragma unroll
        for (int off = 16; off; off >>= 1) s += __shfl_xor_sync(0xffffffffu, s, off);
        if (lane == 0) d_alog[n] = s;
    }
}

// ---------------- softmax over 576 regions (one block) ----------------
__global__ void softmax_kernel()
{
    __shared__ float red[1024];
    int t = threadIdx.x;
    float lv = 0.f, logit = -1e30f;
    if (t < NR) { lv = d_alog[t]; logit = lv; }
    red[t] = logit;
    __syncthreads();
    for (int s = 512; s; s >>= 1) { if (t < s) red[t] = fmaxf(red[t], red[t + s]); __syncthreads(); }
    float mx = red[0];
    __syncthreads();
    float e = (t < NR) ? expf(lv - mx) : 0.f;
    red[t] = e;
    __syncthreads();
    for (int s = 512; s; s >>= 1) { if (t < s) red[t] += red[t + s]; __syncthreads(); }
    float inv = 1.f / red[0];
    if (t < NR) d_aw[t] = e * inv;
}

// ---------------- attended v partials: 18 row-chunks ----------------
__global__ void apply_part_kernel(const float* __restrict__ V)
{
    int rc  = blockIdx.y;                          // 0..17
    int col = blockIdx.x * 256 + threadIdx.x;      // 0..2047
    __shared__ float aw[32];
    if (threadIdx.x < 32) aw[threadIdx.x] = d_aw[rc * 32 + threadIdx.x];
    __syncthreads();
    const float* Vp = V + (size_t)rc * 32 * IMG + col;
    float s = 0.f;
    #pragma unroll 8
    for (int i = 0; i < 32; i++) s += aw[i] * Vp[(size_t)i * IMG];
    d_x2part[rc * IMG + col] = s;
}

__global__ void apply_reduce_kernel()
{
    int j = blockIdx.x * 256 + threadIdx.x;        // 0..2047
    float s = 0.f;
    #pragma unroll
    for (int rc = 0; rc < RCHUNKS; rc++) s += d_x2part[rc * IMG + j];
    d_x2[j] = s;
}

// ---------------- launch ----------------
extern "C" void kernel_launch(void* const* d_in, const int* in_sizes, int n_in,
                              void* d_out, int out_size)
{
    const float* V      = (const float*)d_in[0];
    const int*   w      = (const int*)  d_in[1];
    const float* h1     = (const float*)d_in[2];
    const float* c1     = (const float*)d_in[3];
    const float* h2     = (const float*)d_in[4];
    const float* c2     = (const float*)d_in[5];
    const float* emb    = (const float*)d_in[6];
    const float* W_ih1  = (const float*)d_in[7];
    const float* W_hh1  = (const float*)d_in[8];
    const float* b_ih1  = (const float*)d_in[9];
    const float* b_hh1  = (const float*)d_in[10];
    const float* W_ih2  = (const float*)d_in[11];
    const float* W_hh2  = (const float*)d_in[12];
    const float* b_ih2  = (const float*)d_in[13];
    const float* b_hh2  = (const float*)d_in[14];
    const float* lv_w   = (const float*)d_in[15];
    const float* lv_b   = (const float*)d_in[16];
    const float* lh_w   = (const float*)d_in[17];
    const float* lh_b   = (const float*)d_in[18];
    const float* att_w  = (const float*)d_in[19];
    const float* lin_w  = (const float*)d_in[21];
    const float* lin_b  = (const float*)d_in[22];

    float* out     = (float*)d_out;
    float* o_out   = out;            // 32000
    float* h1n_out = out + 32000;
    float* c1n_out = out + 33024;
    float* h2n_out = out + 34048;
    float* c2n_out = out + 35072;

    static cudaStream_t s_side = nullptr;
    static cudaEvent_t ev_fork = nullptr, ev_join = nullptr;
    if (!s_side) {
        cudaStreamCreateWithFlags(&s_side, cudaStreamNonBlocking);
        cudaEventCreateWithFlags(&ev_fork, cudaEventDisableTiming);
        cudaEventCreateWithFlags(&ev_join, cudaEventDisableTiming);
    }

    // ---- fork: attention GEMM (depends only on V, lv_w) on side stream ----
    cudaEventRecord(ev_fork, 0);
    cudaStreamWaitEvent(s_side, ev_fork, 0);
    {
        dim3 agrid(36, 32);
        attn_gemm_kernel<<<agrid, 128, 0, s_side>>>(V, lv_w);
    }
    cudaEventRecord(ev_join, s_side);

    // ---- main chain: LSTM1 path ----
    vbar_part_kernel<<<dim3(8, RCHUNKS), 256>>>(V);
    x1_kernel<<<16, 256>>>(w, h2, emb);

    matvec2_kernel<<<1024, 256, (4096 + 1024) * sizeof(float)>>>(
        (const float4*)W_ih1, 4096 / 4, (const float4*)W_hh1, 1024 / 4,
        SRC_X1, h1, b_ih1, b_hh1);

    lstm_cell_kernel<<<4, 256>>>(c1, h1n_out, c1n_out, 1);

    h1t_kernel<<<512, 128>>>((const float4*)lh_w, lh_b);

    // ---- join: logits need vt + h1t ----
    cudaStreamWaitEvent(0, ev_join, 0);
    logits_kernel<<<36, 128>>>(lv_b, att_w);
    softmax_kernel<<<1, 1024>>>();
    apply_part_kernel<<<dim3(8, RCHUNKS), 256>>>(V);
    apply_reduce_kernel<<<8, 256>>>();

    matvec2_kernel<<<1024, 256, (3072 + 1024) * sizeof(float)>>>(
        (const float4*)W_ih2, 3072 / 4, (const float4*)W_hh2, 1024 / 4,
        SRC_X2, h2, b_ih2, b_hh2);

    lstm_cell_kernel<<<4, 256>>>(c2, h2n_out, c2n_out, 2);

    lin_kernel<<<4000, 256>>>((const float4*)lin_w, lin_b, o_out, 32000);
}

// round 17
// speedup vs baseline: 1.9896x; 1.1941x over previous
#include <cuda_runtime.h>
#include <math.h>

#define EMBED 1024
#define H1D   1024
#define H2D   1024
#define IMG   2048
#define MIDD  512
#define VOCAB 32000
#define NR    576
#define RCHUNKS 18            // 576 / 32

// ---------------- scratch (device globals; no allocations) ----------------
__device__ float d_x1[4096];             // [h2 | vbar | we]
__device__ float d_g[4096];              // gate pre-activations
__device__ float d_g1pre[4096];          // W_hh1@h1 + b_ih1 + b_hh1
__device__ float d_g2pre[4096];          // W_hh2@h2 + b_ih2 + b_hh2
__device__ float d_h1n[H1D];
__device__ float d_h1t[MIDD];
__device__ float d_vt[NR * MIDD];        // raw attention GEMM result
__device__ float d_alog[NR];             // attention logits
__device__ float d_aw[NR];               // softmax weights
__device__ float d_vpart[RCHUNKS * IMG]; // vbar partials
__device__ float d_x2part[RCHUNKS * IMG];// attended-v partials
__device__ float d_x2[IMG + H1D];        // [v | h1n]
__device__ float d_h2n[H2D];

#define SRC_X1  0
#define SRC_X2  2
__device__ __forceinline__ const float* sel_src(int s) {
    return (s == SRC_X1) ? d_x1 : d_x2;
}
#define PRE_G1 0
#define PRE_G2 1
__device__ __forceinline__ const float* sel_pre(int s) {
    return (s == PRE_G1) ? d_g1pre : d_g2pre;
}

// ---------------- vbar partials: 18 row-chunks x 2048 cols ----------------
__global__ void vbar_part_kernel(const float* __restrict__ V)
{
    int rc  = blockIdx.y;                          // 0..17
    int col = blockIdx.x * 256 + threadIdx.x;      // 0..2047
    const float* Vp = V + (size_t)rc * 32 * IMG + col;
    float s = 0.f;
    #pragma unroll 8
    for (int i = 0; i < 32; i++) s += Vp[(size_t)i * IMG];
    d_vpart[rc * IMG + col] = s;
}

// ---------------- x1 = [h2 | vbar | emb[w]] ----------------
__global__ void x1_kernel(const int* __restrict__ w, const float* __restrict__ h2,
                          const float* __restrict__ emb)
{
    int j = blockIdx.x * blockDim.x + threadIdx.x;   // 0..4095
    if (j < 1024) {
        d_x1[j] = h2[j];
    } else if (j < 1024 + IMG) {
        int c = j - 1024;
        float s = 0.f;
        #pragma unroll
        for (int rc = 0; rc < RCHUNKS; rc++) s += d_vpart[rc * IMG + c];
        d_x1[j] = s * (1.0f / NR);
    } else if (j < 4096) {
        d_x1[j] = emb[(size_t)w[0] * EMBED + (j - (1024 + IMG))];
    }
}

// ---- hh precompute: out[r] = W[r,:1024] @ v + b1[r] + b2[r]  (warp/row) ----
__global__ void hh_kernel(const float4* __restrict__ W, const float* __restrict__ v,
                          const float* __restrict__ b1, const float* __restrict__ b2,
                          int dst_sel)
{
    __shared__ float xs[1024];
    int tid = threadIdx.x;
    for (int i = tid; i < 1024; i += blockDim.x) xs[i] = v[i];
    __syncthreads();

    int warp = tid >> 5, lane = tid & 31;
    int r = blockIdx.x * 8 + warp;                 // grid 512 -> 4096 rows
    const float4* xs4 = (const float4*)xs;
    const float4* Wr = W + (size_t)r * 256;
    float4 a[8];
    #pragma unroll
    for (int u = 0; u < 8; u++) a[u] = __ldcs(Wr + lane + u * 32);
    float acc = 0.f;
    #pragma unroll
    for (int u = 0; u < 8; u++) {
        float4 x = xs4[lane + u * 32];
        acc += a[u].x * x.x + a[u].y * x.y + a[u].z * x.z + a[u].w * x.w;
    }
    #pragma unroll
    for (int off = 16; off; off >>= 1) acc += __shfl_xor_sync(0xffffffffu, acc, off);
    if (lane == 0) {
        float* outp = (dst_sel == PRE_G1) ? d_g1pre : d_g2pre;
        outp[r] = acc + b1[r] + b2[r];
    }
}

// ---- gate matvec, K-split-2: d_g[r] = W[r,:]@x + pre[r]  (2 warps/row) ----
__global__ void mv2p_kernel(const float4* __restrict__ W, int C4,
                            int src_sel, int pre_sel)
{
    extern __shared__ float xs[];
    __shared__ float sp[8];
    const float* v1 = sel_src(src_sel);
    int tid = threadIdx.x;
    for (int i = tid; i < C4 * 4; i += blockDim.x) xs[i] = v1[i];
    __syncthreads();

    const int warp = tid >> 5, lane = tid & 31;
    const int row  = blockIdx.x * 4 + (warp >> 1);
    const int half = warp & 1;
    const float4* xs4 = (const float4*)xs;

    float acc = 0.f;
    const int Ch = C4 >> 1;
    const float4* Wr = W + (size_t)row * C4 + half * Ch;
    const float4* xh = xs4 + half * Ch;
    int i = lane;
    for (; i + 7 * 32 < Ch; i += 8 * 32) {
        float4 a[8];
        #pragma unroll
        for (int u = 0; u < 8; u++) a[u] = __ldcs(Wr + i + u * 32);
        #pragma unroll
        for (int u = 0; u < 8; u++) {
            float4 x = xh[i + u * 32];
            acc += a[u].x * x.x + a[u].y * x.y + a[u].z * x.z + a[u].w * x.w;
        }
    }
    for (; i < Ch; i += 32) {
        float4 a = __ldcs(Wr + i), x = xh[i];
        acc += a.x * x.x + a.y * x.y + a.z * x.z + a.w * x.w;
    }
    #pragma unroll
    for (int off = 16; off; off >>= 1) acc += __shfl_xor_sync(0xffffffffu, acc, off);
    if (lane == 0) sp[warp] = acc;
    __syncthreads();
    if (tid < 4) {
        int r = blockIdx.x * 4 + tid;
        d_g[r] = sp[2 * tid] + sp[2 * tid + 1] + sel_pre(pre_sel)[r];
    }
}

// ---- vocab projection: warp-per-row ----
__global__ void lin_kernel(const float4* __restrict__ W, const float* __restrict__ b,
                           float* __restrict__ out, int R)
{
    __shared__ float xs[H2D];
    int tid = threadIdx.x;
    for (int i = tid; i < H2D; i += blockDim.x) xs[i] = d_h2n[i];
    __syncthreads();

    int warp = tid >> 5, lane = tid & 31;
    int r = blockIdx.x * (blockDim.x >> 5) + warp;
    if (r >= R) return;

    const float4* xs4 = (const float4*)xs;
    const float4* Wr = W + (size_t)r * 256;
    float4 a[8];
    #pragma unroll
    for (int u = 0; u < 8; u++) a[u] = __ldcs(Wr + lane + u * 32);
    float acc = 0.f;
    #pragma unroll
    for (int u = 0; u < 8; u++) {
        float4 x = xs4[lane + u * 32];
        acc += a[u].x * x.x + a[u].y * x.y + a[u].z * x.z + a[u].w * x.w;
    }
    #pragma unroll
    for (int off = 16; off; off >>= 1) acc += __shfl_xor_sync(0xffffffffu, acc, off);
    if (lane == 0) out[r] = acc + b[r];
}

// ---------------- h1t = lh_w @ h1n + lh_b  (block per row) ----------------
__global__ void h1t_kernel(const float4* __restrict__ lh_w, const float* __restrict__ lh_b)
{
    int r = blockIdx.x;                 // 0..511
    int t = threadIdx.x;                // 0..127
    const float4* Wr = lh_w + (size_t)r * 256;
    const float4* x4 = (const float4*)d_h1n;
    float4 a0 = Wr[t], a1 = Wr[t + 128];
    float4 x0 = x4[t], x1 = x4[t + 128];
    float s = a0.x * x0.x + a0.y * x0.y + a0.z * x0.z + a0.w * x0.w
            + a1.x * x1.x + a1.y * x1.y + a1.z * x1.z + a1.w * x1.w;
    #pragma unroll
    for (int o = 16; o; o >>= 1) s += __shfl_xor_sync(0xffffffffu, s, o);
    __shared__ float ws[4];
    if ((t & 31) == 0) ws[t >> 5] = s;
    __syncthreads();
    if (t == 0) d_h1t[r] = ws[0] + ws[1] + ws[2] + ws[3] + lh_b[r];
}

// ---------------- LSTM cell from d_g (gate order i,f,g,o) ----------------
__global__ void lstm_cell_kernel(const float* __restrict__ c_old,
                                 float* __restrict__ hA, float* __restrict__ cA,
                                 int which)
{
    int j = blockIdx.x * blockDim.x + threadIdx.x;   // 0..1023
    float gi = d_g[j], gf = d_g[1024 + j], gg = d_g[2048 + j], go = d_g[3072 + j];
    float i = 1.f / (1.f + expf(-gi));
    float f = 1.f / (1.f + expf(-gf));
    float o = 1.f / (1.f + expf(-go));
    float c = f * c_old[j] + i * tanhf(gg);
    float h = o * tanhf(c);
    cA[j] = c;
    hA[j] = h;
    if (which == 1) {
        d_h1n[j] = h;
        d_x2[IMG + j] = h;
    } else {
        d_h2n[j] = h;
    }
}

// ---------------- attention GEMM: vt[n][m] = V[n,:] . lv_w[m,:] ----------------
// 16 regions x 16 mids per block; 4 warps each own 4 mids; lanes split K.
// Accumulators stay in registers: all indexing is compile-time constant.
__global__ void __launch_bounds__(128) attn_gemm_kernel(const float* __restrict__ V,
                                                        const float* __restrict__ lv_w)
{
    const int rb   = blockIdx.x;           // 0..35
    const int mb   = blockIdx.y;           // 0..31
    const int w    = threadIdx.x >> 5;
    const int lane = threadIdx.x & 31;
    const int r0 = rb * 16;
    const int m0 = mb * 16 + w * 4;

    __shared__ float Vs[16][128];

    float acc[4][16];
    #pragma unroll
    for (int mi = 0; mi < 4; mi++)
        #pragma unroll
        for (int r = 0; r < 16; r++) acc[mi][r] = 0.f;

    for (int k0 = 0; k0 < IMG; k0 += 128) {
        __syncthreads();
        #pragma unroll
        for (int jj = 0; jj < 16; jj++)
            Vs[jj][threadIdx.x] = V[(size_t)(r0 + jj) * IMG + k0 + threadIdx.x];
        __syncthreads();

        #pragma unroll
        for (int kk4 = 0; kk4 < 4; kk4++) {
            int kk = kk4 * 32 + lane;
            float lw[4];
            #pragma unroll
            for (int mi = 0; mi < 4; mi++)
                lw[mi] = lv_w[(size_t)(m0 + mi) * IMG + k0 + kk];
            #pragma unroll
            for (int r = 0; r < 16; r++) {
                float v = Vs[r][kk];
                #pragma unroll
                for (int mi = 0; mi < 4; mi++) acc[mi][r] += lw[mi] * v;
            }
        }
    }

    // lane all-reduce (K slices) -> lane-uniform values
    #pragma unroll
    for (int mi = 0; mi < 4; mi++)
        #pragma unroll
        for (int r = 0; r < 16; r++) {
            float s = acc[mi][r];
            #pragma unroll
            for (int off = 16; off; off >>= 1) s += __shfl_xor_sync(0xffffffffu, s, off);
            acc[mi][r] = s;
        }

    // statically-indexed predicated stores (keeps acc in registers)
    #pragma unroll
    for (int r = 0; r < 16; r++) {
        if (lane == r) {
            #pragma unroll
            for (int mi = 0; mi < 4; mi++)
                d_vt[(size_t)(r0 + r) * MIDD + m0 + mi] = acc[mi][r];
        }
    }
}

// ---------------- logits (att_b dropped: softmax-invariant) ----------------
__global__ void logits_kernel(const float* __restrict__ lv_b,
                              const float* __restrict__ att_w)
{
    __shared__ float hb[MIDD];
    __shared__ float aww[MIDD];
    for (int i = threadIdx.x; i < MIDD; i += 128) {
        hb[i]  = d_h1t[i] + lv_b[i];
        aww[i] = att_w[i];
    }
    __syncthreads();
    int warp = threadIdx.x >> 5, lane = threadIdx.x & 31;
    int wg = blockIdx.x * 4 + warp;        // 0..143
    #pragma unroll
    for (int q = 0; q < 4; q++) {
        int n = wg * 4 + q;                // 0..575
        const float* vtn = d_vt + (size_t)n * MIDD;
        float s = 0.f;
        for (int m = lane; m < MIDD; m += 32)
            s += aww[m] * tanhf(vtn[m] + hb[m]);
        #pragma unroll
        for (int off = 16; off; off >>= 1) s += __shfl_xor_sync(0xffffffffu, s, off);
        if (lane == 0) d_alog[n] = s;
    }
}

// ---------------- softmax over 576 regions (one block) ----------------
__global__ void softmax_kernel()
{
    __shared__ float red[1024];
    int t = threadIdx.x;
    float lv = 0.f, logit = -1e30f;
    if (t < NR) { lv = d_alog[t]; logit = lv; }
    red[t] = logit;
    __syncthreads();
    for (int s = 512; s; s >>= 1) { if (t < s) red[t] = fmaxf(red[t], red[t + s]); __syncthreads(); }
    float mx = red[0];
    __syncthreads();
    float e = (t < NR) ? expf(lv - mx) : 0.f;
    red[t] = e;
    __syncthreads();
    for (int s = 512; s; s >>= 1) { if (t < s) red[t] += red[t + s]; __syncthreads(); }
    float inv = 1.f / red[0];
    if (t < NR) d_aw[t] = e * inv;
}

// ---------------- attended v partials: 18 row-chunks ----------------
__global__ void apply_part_kernel(const float* __restrict__ V)
{
    int rc  = blockIdx.y;                          // 0..17
    int col = blockIdx.x * 256 + threadIdx.x;      // 0..2047
    __shared__ float aw[32];
    if (threadIdx.x < 32) aw[threadIdx.x] = d_aw[rc * 32 + threadIdx.x];
    __syncthreads();
    const float* Vp = V + (size_t)rc * 32 * IMG + col;
    float s = 0.f;
    #pragma unroll 8
    for (int i = 0; i < 32; i++) s += aw[i] * Vp[(size_t)i * IMG];
    d_x2part[rc * IMG + col] = s;
}

__global__ void apply_reduce_kernel()
{
    int j = blockIdx.x * 256 + threadIdx.x;        // 0..2047
    float s = 0.f;
    #pragma unroll
    for (int rc = 0; rc < RCHUNKS; rc++) s += d_x2part[rc * IMG + j];
    d_x2[j] = s;
}

// ---------------- launch ----------------
extern "C" void kernel_launch(void* const* d_in, const int* in_sizes, int n_in,
                              void* d_out, int out_size)
{
    const float* V      = (const float*)d_in[0];
    const int*   w      = (const int*)  d_in[1];
    const float* h1     = (const float*)d_in[2];
    const float* c1     = (const float*)d_in[3];
    const float* h2     = (const float*)d_in[4];
    const float* c2     = (const float*)d_in[5];
    const float* emb    = (const float*)d_in[6];
    const float* W_ih1  = (const float*)d_in[7];
    const float* W_hh1  = (const float*)d_in[8];
    const float* b_ih1  = (const float*)d_in[9];
    const float* b_hh1  = (const float*)d_in[10];
    const float* W_ih2  = (const float*)d_in[11];
    const float* W_hh2  = (const float*)d_in[12];
    const float* b_ih2  = (const float*)d_in[13];
    const float* b_hh2  = (const float*)d_in[14];
    const float* lv_w   = (const float*)d_in[15];
    const float* lv_b   = (const float*)d_in[16];
    const float* lh_w   = (const float*)d_in[17];
    const float* lh_b   = (const float*)d_in[18];
    const float* att_w  = (const float*)d_in[19];
    const float* lin_w  = (const float*)d_in[21];
    const float* lin_b  = (const float*)d_in[22];

    float* out     = (float*)d_out;
    float* o_out   = out;            // 32000
    float* h1n_out = out + 32000;
    float* c1n_out = out + 33024;
    float* h2n_out = out + 34048;
    float* c2n_out = out + 35072;

    static cudaStream_t s_attn = nullptr, s_hh = nullptr;
    static cudaEvent_t ev_fork = nullptr, ev_attn = nullptr, ev_hh1 = nullptr, ev_hh2 = nullptr;
    if (!s_attn) {
        cudaStreamCreateWithFlags(&s_attn, cudaStreamNonBlocking);
        cudaStreamCreateWithFlags(&s_hh, cudaStreamNonBlocking);
        cudaEventCreateWithFlags(&ev_fork, cudaEventDisableTiming);
        cudaEventCreateWithFlags(&ev_attn, cudaEventDisableTiming);
        cudaEventCreateWithFlags(&ev_hh1, cudaEventDisableTiming);
        cudaEventCreateWithFlags(&ev_hh2, cudaEventDisableTiming);
    }

    cudaEventRecord(ev_fork, 0);

    // ---- side stream A: attention GEMM (depends only on V, lv_w) ----
    cudaStreamWaitEvent(s_attn, ev_fork, 0);
    {
        dim3 agrid(36, 32);
        attn_gemm_kernel<<<agrid, 128, 0, s_attn>>>(V, lv_w);
    }
    cudaEventRecord(ev_attn, s_attn);

    // ---- side stream B: hidden-state halves of both LSTM gate matvecs ----
    cudaStreamWaitEvent(s_hh, ev_fork, 0);
    hh_kernel<<<512, 256, 0, s_hh>>>((const float4*)W_hh1, h1, b_ih1, b_hh1, PRE_G1);
    cudaEventRecord(ev_hh1, s_hh);
    hh_kernel<<<512, 256, 0, s_hh>>>((const float4*)W_hh2, h2, b_ih2, b_hh2, PRE_G2);
    cudaEventRecord(ev_hh2, s_hh);

    // ---- main chain ----
    vbar_part_kernel<<<dim3(8, RCHUNKS), 256>>>(V);
    x1_kernel<<<16, 256>>>(w, h2, emb);

    cudaStreamWaitEvent(0, ev_hh1, 0);
    mv2p_kernel<<<1024, 256, 4096 * sizeof(float)>>>(
        (const float4*)W_ih1, 4096 / 4, SRC_X1, PRE_G1);

    lstm_cell_kernel<<<4, 256>>>(c1, h1n_out, c1n_out, 1);

    h1t_kernel<<<512, 128>>>((const float4*)lh_w, lh_b);

    cudaStreamWaitEvent(0, ev_attn, 0);
    logits_kernel<<<36, 128>>>(lv_b, att_w);
    softmax_kernel<<<1, 1024>>>();
    apply_part_kernel<<<dim3(8, RCHUNKS), 256>>>(V);
    apply_reduce_kernel<<<8, 256>>>();

    cudaStreamWaitEvent(0, ev_hh2, 0);
    mv2p_kernel<<<1024, 256, 3072 * sizeof(float)>>>(
        (const float4*)W_ih2, 3072 / 4, SRC_X2, PRE_G2);

    lstm_cell_kernel<<<4, 256>>>(c2, h2n_out, c2n_out, 2);

    lin_kernel<<<4000, 256>>>((const float4*)lin_w, lin_b, o_out, 32000);
}